// round 15
// baseline (speedup 1.0000x reference)
#include <cuda_runtime.h>
#include <cstdint>

// Problem constants (fixed by setup_inputs): x is [8, 512, 16384] fp32.
#define BATCH   8
#define NBANDS  8
#define FBAND   64          // 512 / 8
#define TLEN    16384
#define NDIFF   5
#define NAVG    11
#define NGAUSS  15
#define STRIP   512         // time-strip per k_pool block (128 thr * 4 t)
#define TPB_POOL 128

// Scratch (allocation-free rule: __device__ globals)
__device__ float    g_pool[BATCH * NBANDS * TLEN];   // 4 MB
__device__ float    g_act [BATCH * TLEN];            // 512 KB
__device__ unsigned g_bmax[BATCH];
__device__ __align__(8) float g_zero2[2] = {0.f, 0.f};  // zero-pad page for halos

// log2(1 + gam*v); ln2 is folded into the diff weights so no FMUL-by-ln2 here.
__device__ __forceinline__ float lg2p(float gam, float v) {
    return __log2f(fmaf(gam, v, 1.0f));
}

// ---------------------------------------------------------------------------
// Kernel 1: the 256 MB streamer.
// pool[b,c,t] = sum_f relu( sum_k diff_w[c,k]*log1p(gamma_c*x[b,c*64+f,t+k-2]) + diff_b[c] )
// R15: 4 t/thread -> 262K threads = 8192 warps = ~55 warps/SM (prev configs
// were grid-capped at 27.7). Per row: 1x LDG.128 + 1 halo float, 5 logs;
// manual 1-row software pipeline (proven worth ~2.5us in R14's ablation).
// ---------------------------------------------------------------------------
__global__ void __launch_bounds__(TPB_POOL, 12) k_pool(
    const float* __restrict__ x,
    const float* __restrict__ log_gamma,
    const float* __restrict__ diff_w,      // [NBANDS,1,1,5] flat
    const float* __restrict__ diff_b)
{
    const int slab = blockIdx.y;                 // b*NBANDS + c
    const int c    = slab & (NBANDS - 1);
    const int tid  = threadIdx.x;
    const int t0   = blockIdx.x * STRIP + tid * 4;

    // reset per-batch maxes (k_act consumes them after its grid-dependency sync)
    if (blockIdx.x == 0 && blockIdx.y == 0 && tid < BATCH) g_bmax[tid] = 0u;

    const float gam = __expf(log_gamma[c]);
    const float LN2 = 0.69314718055994531f;      // fold ln2 into weights -> log2f
    const float w0 = diff_w[c * NDIFF + 0] * LN2;
    const float w1 = diff_w[c * NDIFF + 1] * LN2;
    const float w2 = diff_w[c * NDIFF + 2] * LN2;
    const float w3 = diff_w[c * NDIFF + 3] * LN2;
    const float w4 = diff_w[c * NDIFF + 4] * LN2;
    const float db = diff_b[c];

    const float* base = x + (size_t)slab * FBAND * TLEN + t0;

    float acc[4];
    #pragma unroll
    for (int i = 0; i < 4; ++i) acc[i] = 0.f;

    if (w0 == 0.f && w1 == 0.f && w4 == 0.f) {
        // ---------------- sparse hot path: taps 2,3 only ----------------
        // outputs i use logs of t0+i .. t0+i+1 -> window [t0, t0+5): one
        // float4 + ONE right-halo float; left halo not needed at all.
        const bool   okR = (t0 + 4 < TLEN);
        const float* pR  = okR ? (base + 4) : g_zero2;
        const int    sR  = okR ? TLEN : 0;

        float4 a0 = __ldcs(reinterpret_cast<const float4*>(base));
        float  r0 = __ldcs(pR);

        #pragma unroll 4
        for (int f = 0; f < FBAND; ++f) {
            // prefetch next row; clamp so the final re-read is L1-hot
            const int fn = (f < FBAND - 1) ? (f + 1) : f;
            const float4 a1 = __ldcs(reinterpret_cast<const float4*>(base + (size_t)fn * TLEN));
            const float  r1 = __ldcs(pR + (size_t)fn * sR);

            // L[j] = log2(1 + gamma * x[t0 + j]), j = 0..4 (zero page -> 0)
            const float L0 = lg2p(gam, a0.x);
            const float L1 = lg2p(gam, a0.y);
            const float L2 = lg2p(gam, a0.z);
            const float L3 = lg2p(gam, a0.w);
            const float L4 = lg2p(gam, r0);

            // d = w2*log[t+0] + w3*log[t+1] + db  (w0=w1=w4=0 exactly)
            acc[0] += fmaxf(fmaf(w2, L0, fmaf(w3, L1, db)), 0.f);
            acc[1] += fmaxf(fmaf(w2, L1, fmaf(w3, L2, db)), 0.f);
            acc[2] += fmaxf(fmaf(w2, L2, fmaf(w3, L3, db)), 0.f);
            acc[3] += fmaxf(fmaf(w2, L3, fmaf(w3, L4, db)), 0.f);

            a0 = a1; r0 = r1;
        }
    } else {
        // ------------- general fallback (arbitrary 5-tap weights) -------------
        // Register-light scalar path; correct for any diff_w. Never taken for
        // this problem's weights, so performance is irrelevant.
        const float wk[NDIFF] = {w0, w1, w2, w3, w4};
        for (int f = 0; f < FBAND; ++f) {
            const float* p = base + (size_t)f * TLEN;
            #pragma unroll
            for (int i = 0; i < 4; ++i) {
                float d = db;
                #pragma unroll
                for (int k = 0; k < NDIFF; ++k) {
                    const int t = t0 + i + k - 2;
                    float lv = 0.f;
                    if (t >= 0 && t < TLEN)
                        lv = lg2p(gam, __ldg(p + (i + k - 2)));
                    d = fmaf(wk[k], lv, d);
                }
                acc[i] += fmaxf(d, 0.f);
            }
        }
    }

    float* o = g_pool + (size_t)slab * TLEN + t0;
    *reinterpret_cast<float4*>(o) = make_float4(acc[0], acc[1], acc[2], acc[3]);
}

// ---------------------------------------------------------------------------
// Kernel 2: mix + avg + gauss + relu + per-batch max. Wide grid (16 x 8 blocks).
// Launched with PDL: prologue (weight loads) overlaps k_pool's drain; the
// grid-dependency sync gates only the g_pool/g_bmax accesses.
// ---------------------------------------------------------------------------
#define ACHUNK 1024
#define UH 12      // 5 (avg) + 7 (gauss)
#define MH 7

__global__ void __launch_bounds__(256) k_act(
    const float* __restrict__ avg_w,    // [8,1,11] flat; band-0 taps (uniform)
    const float* __restrict__ avg_b,
    const float* __restrict__ mix_w,
    const float* __restrict__ gauss_w,  // [1,1,15] flat
    const float* __restrict__ gauss_b)
{
    __shared__ float su[ACHUNK + 2 * UH];
    __shared__ float sm[ACHUNK + 2 * MH];
    __shared__ float sred[8];

    const int b   = blockIdx.y;
    const int t0  = blockIdx.x * ACHUNK;
    const int tid = threadIdx.x;

    // prologue: everything here reads only kernel inputs (not k_pool outputs)
    float mw[NBANDS];
    #pragma unroll
    for (int c = 0; c < NBANDS; ++c) mw[c] = mix_w[c];
    float aw[NAVG];
    #pragma unroll
    for (int k = 0; k < NAVG; ++k) aw[k] = avg_w[k];
    float CB = 0.f;
    #pragma unroll
    for (int c = 0; c < NBANDS; ++c) CB = fmaf(mw[c], avg_b[c], CB);
    float gw[NGAUSS];
    #pragma unroll
    for (int k = 0; k < NGAUSS; ++k) gw[k] = gauss_w[k];
    const float gb = gauss_b[0];

    // wait for k_pool's grid (PDL); makes its g_pool/g_bmax writes visible
    cudaGridDependencySynchronize();

    const float* pb = g_pool + (size_t)b * NBANDS * TLEN;

    // stage u chunk + halo (zero-padded outside [0, TLEN)); u computed on the fly
    for (int i = tid; i < ACHUNK + 2 * UH; i += 256) {
        const int gt = t0 - UH + i;
        float v = 0.f;
        if (gt >= 0 && gt < TLEN) {
            #pragma unroll
            for (int c = 0; c < NBANDS; ++c)
                v = fmaf(mw[c], pb[c * TLEN + gt], v);
        }
        su[i] = v;
    }
    __syncthreads();

    // m chunk + halo (m zero-padded outside [0, TLEN) for the gauss conv)
    for (int i = tid; i < ACHUNK + 2 * MH; i += 256) {
        const int gt = t0 - MH + i;
        float mval = 0.f;
        if (gt >= 0 && gt < TLEN) {
            const int bidx = i + (UH - MH);   // su index of global gt
            float a = 0.f;
            #pragma unroll
            for (int k = 0; k < NAVG; ++k)
                a = fmaf(aw[k], su[bidx + k - 5], a);
            mval = su[bidx] - a - CB;
        }
        sm[i] = mval;
    }
    __syncthreads();

    float mx = 0.f;
    float* ao = g_act + (size_t)b * TLEN + t0;
    #pragma unroll
    for (int j = 0; j < ACHUNK / 256; ++j) {
        const int tl = tid + j * 256;
        float g = gb;
        #pragma unroll
        for (int k = 0; k < NGAUSS; ++k)
            g = fmaf(gw[k], sm[tl + k], g);
        const float a = fmaxf(g, 0.f);
        ao[tl] = a;
        mx = fmaxf(mx, a);
    }

    // block max reduce -> atomicMax (values >= 0, so uint order == float order)
    #pragma unroll
    for (int o = 16; o > 0; o >>= 1)
        mx = fmaxf(mx, __shfl_xor_sync(0xffffffffu, mx, o));
    if ((tid & 31) == 0) sred[tid >> 5] = mx;
    __syncthreads();
    if (tid < 8) {
        mx = sred[tid];
        #pragma unroll
        for (int o = 4; o > 0; o >>= 1)
            mx = fmaxf(mx, __shfl_xor_sync(0xffu, mx, o));
        if (tid == 0) atomicMax(&g_bmax[b], __float_as_uint(mx));
    }
}

// ---------------------------------------------------------------------------
// Kernel 3: out = act / (max_b + 1e-8). Also PDL-gated on k_act.
// ---------------------------------------------------------------------------
__global__ void __launch_bounds__(256) k_norm(float* __restrict__ out)
{
    const int v = blockIdx.x * 256 + threadIdx.x;   // float4 index over BATCH*TLEN/4
    const int b = v / (TLEN / 4);

    cudaGridDependencySynchronize();   // wait for k_act's g_act / g_bmax

    const float mxv = __uint_as_float(g_bmax[b]);
    const float inv = 1.0f / (mxv + 1e-8f);
    float4 q = reinterpret_cast<const float4*>(g_act)[v];
    q.x *= inv; q.y *= inv; q.z *= inv; q.w *= inv;
    reinterpret_cast<float4*>(out)[v] = q;
}

// ---------------------------------------------------------------------------
// Inputs (metadata order): x, log_gamma, diff_w, diff_b, avg_w, avg_b,
//                          mix_w, gauss_w, gauss_b. Output: [8, 16384] fp32.
// ---------------------------------------------------------------------------
extern "C" void kernel_launch(void* const* d_in, const int* in_sizes, int n_in,
                              void* d_out, int out_size)
{
    const float* x         = (const float*)d_in[0];
    const float* log_gamma = (const float*)d_in[1];
    const float* diff_w    = (const float*)d_in[2];
    const float* diff_b    = (const float*)d_in[3];
    const float* avg_w     = (const float*)d_in[4];
    const float* avg_b     = (const float*)d_in[5];
    const float* mix_w     = (const float*)d_in[6];
    const float* gauss_w   = (const float*)d_in[7];
    const float* gauss_b   = (const float*)d_in[8];
    float* out = (float*)d_out;

    // 2048 blocks x 128 threads = 8192 warps (~55/SM available).
    k_pool<<<dim3(TLEN / STRIP, BATCH * NBANDS), TPB_POOL>>>(x, log_gamma, diff_w, diff_b);

    // PDL: overlap tail-kernel launch ramps with the upstream kernel's drain.
    cudaLaunchAttribute pdl[1];
    pdl[0].id = cudaLaunchAttributeProgrammaticStreamSerialization;
    pdl[0].val.programmaticStreamSerializationAllowed = 1;

    {
        cudaLaunchConfig_t cfg = {};
        cfg.gridDim  = dim3(TLEN / ACHUNK, BATCH);
        cfg.blockDim = dim3(256);
        cfg.attrs    = pdl;
        cfg.numAttrs = 1;
        cudaLaunchKernelEx(&cfg, k_act, avg_w, avg_b, mix_w, gauss_w, gauss_b);
    }
    {
        cudaLaunchConfig_t cfg = {};
        cfg.gridDim  = dim3(BATCH * TLEN / 4 / 256);
        cfg.blockDim = dim3(256);
        cfg.attrs    = pdl;
        cfg.numAttrs = 1;
        cudaLaunchKernelEx(&cfg, k_norm, out);
    }
}

// round 16
// speedup vs baseline: 1.2239x; 1.2239x over previous
#include <cuda_runtime.h>
#include <cstdint>

// Problem constants (fixed by setup_inputs): x is [8, 512, 16384] fp32.
#define BATCH   8
#define NBANDS  8
#define FBAND   64          // 512 / 8
#define TLEN    16384
#define NDIFF   5
#define NAVG    11
#define NGAUSS  15
#define STRIP   512         // time-strip per k_pool block (64 thr * 8 t)
#define TPB_POOL 64

#define ACHUNK  1024
#define NBLK_TAIL ((TLEN / ACHUNK) * BATCH)   // 128 tail blocks (1 per SM max)

// Scratch (allocation-free rule: __device__ globals)
__device__ float    g_pool[BATCH * NBANDS * TLEN];   // 4 MB
__device__ unsigned g_bmax[BATCH];
__device__ unsigned g_sync;                          // tail spin-barrier counter
__device__ __align__(8) float g_zero2[2] = {0.f, 0.f};  // zero-pad page for halos

// log2(1 + gam*v); ln2 is folded into the diff weights so no FMUL-by-ln2 here.
__device__ __forceinline__ float lg2p(float gam, float v) {
    return __log2f(fmaf(gam, v, 1.0f));
}

// ---------------------------------------------------------------------------
// Kernel 1: the 256 MB streamer — the converged R11 shape (measured 44.1us,
// 6.27 TB/s ~= the LTS chip cap; reproduced across 3 rounds).
// pool[b,c,t] = sum_f relu( sum_k diff_w[c,k]*log1p(gamma_c*x[b,c*64+f,t+k-2]) + diff_b[c] )
// Thread owns 8 contiguous t: 2x LDG.128 + 1 halo float per row, 9 logs/row,
// 1-row-deep manual pipeline. 2048 blocks x 64 threads.
// ---------------------------------------------------------------------------
__global__ void __launch_bounds__(TPB_POOL, 16) k_pool(
    const float* __restrict__ x,
    const float* __restrict__ log_gamma,
    const float* __restrict__ diff_w,      // [NBANDS,1,1,5] flat
    const float* __restrict__ diff_b)
{
    const int slab = blockIdx.y;                 // b*NBANDS + c
    const int c    = slab & (NBANDS - 1);
    const int tid  = threadIdx.x;
    const int t0   = blockIdx.x * STRIP + tid * 8;

    // reset tail state (k_tail consumes after its grid-dependency sync)
    if (blockIdx.x == 0 && blockIdx.y == 0 && tid < BATCH + 1) {
        if (tid < BATCH) g_bmax[tid] = 0u; else g_sync = 0u;
    }

    const float gam = __expf(log_gamma[c]);
    const float LN2 = 0.69314718055994531f;      // fold ln2 into weights -> log2f
    const float w0 = diff_w[c * NDIFF + 0] * LN2;
    const float w1 = diff_w[c * NDIFF + 1] * LN2;
    const float w2 = diff_w[c * NDIFF + 2] * LN2;
    const float w3 = diff_w[c * NDIFF + 3] * LN2;
    const float w4 = diff_w[c * NDIFF + 4] * LN2;
    const float db = diff_b[c];

    const float* base = x + (size_t)slab * FBAND * TLEN + t0;

    const bool okR = (t0 + 8 < TLEN);

    float acc[8];
    #pragma unroll
    for (int i = 0; i < 8; ++i) acc[i] = 0.f;

    if (w0 == 0.f && w1 == 0.f && w4 == 0.f) {
        // ---------------- sparse hot path: taps 2,3 only ----------------
        // outputs i use logs of t0+i .. t0+i+1 -> window [t0, t0+9): only ONE
        // right-halo float needed; left halo not needed at all.
        const float* pR = okR ? (base + 8) : g_zero2;
        const int    sR = okR ? TLEN : 0;

        float4 a0 = __ldcs(reinterpret_cast<const float4*>(base));
        float4 b0 = __ldcs(reinterpret_cast<const float4*>(base + 4));
        float  r0 = __ldcs(pR);

        #pragma unroll 2
        for (int f = 0; f < FBAND; ++f) {
            const int fn = (f + 1) & (FBAND - 1);   // wrap-clamped prefetch
            const float4 a1 = __ldcs(reinterpret_cast<const float4*>(base + (size_t)fn * TLEN));
            const float4 b1 = __ldcs(reinterpret_cast<const float4*>(base + (size_t)fn * TLEN + 4));
            const float  r1 = __ldcs(pR + (size_t)fn * sR);

            // L[j] = log2(1 + gamma * x[t0 + j]), j = 0..8 (zero page -> 0)
            float L[9];
            L[0] = lg2p(gam, a0.x);  L[1] = lg2p(gam, a0.y);
            L[2] = lg2p(gam, a0.z);  L[3] = lg2p(gam, a0.w);
            L[4] = lg2p(gam, b0.x);  L[5] = lg2p(gam, b0.y);
            L[6] = lg2p(gam, b0.z);  L[7] = lg2p(gam, b0.w);
            L[8] = lg2p(gam, r0);

            #pragma unroll
            for (int i = 0; i < 8; ++i) {
                // d = w2*log[t+0] + w3*log[t+1] + db  (w0=w1=w4=0 exactly)
                float d = fmaf(w2, L[i], fmaf(w3, L[i + 1], db));
                acc[i] += fmaxf(d, 0.f);   // A_LRELU = 0 -> relu
            }
            a0 = a1; b0 = b1; r0 = r1;
        }
    } else {
        // ------------- general fallback (arbitrary 5-tap weights) -------------
        // Register-light scalar path; correct for any diff_w. Never taken for
        // this problem's weights, so performance is irrelevant.
        const float wk[NDIFF] = {w0, w1, w2, w3, w4};
        for (int f = 0; f < FBAND; ++f) {
            const float* p = base + (size_t)f * TLEN;
            #pragma unroll
            for (int i = 0; i < 8; ++i) {
                float d = db;
                #pragma unroll
                for (int k = 0; k < NDIFF; ++k) {
                    const int t = t0 + i + k - 2;
                    float lv = 0.f;
                    if (t >= 0 && t < TLEN)
                        lv = lg2p(gam, __ldg(p + (i + k - 2)));
                    d = fmaf(wk[k], lv, d);
                }
                acc[i] += fmaxf(d, 0.f);
            }
        }
    }

    float* o = g_pool + (size_t)slab * TLEN + t0;
    *reinterpret_cast<float4*>(o)     = make_float4(acc[0], acc[1], acc[2], acc[3]);
    *reinterpret_cast<float4*>(o + 4) = make_float4(acc[4], acc[5], acc[6], acc[7]);
}

// ---------------------------------------------------------------------------
// Kernel 2: FUSED tail (PDL). 128 blocks x 256 thr, <=1 per SM.
//   u[t] = sum_c mix_w[c]*pool[b,c,t]
//   m[t] = u[t] - (avg_w (x) u)[t] - sum_c mw[c]*avg_b[c]   (band-uniform avg_w)
//   act  = relu((gauss_w (x) m)[t] + gauss_b)   (held in 4 regs/thread)
//   atomicMax per batch -> 128-block spin barrier -> out = act/(max_b + 1e-8)
// PDL safety: blocks first wait in cudaGridDependencySynchronize; once k_pool
// completes all SMs are free, so all 128 blocks are resident before any can
// pass the spin barrier (no deadlock).
// ---------------------------------------------------------------------------
#define UH 12      // 5 (avg) + 7 (gauss)
#define MH 7

__global__ void __launch_bounds__(256) k_tail(
    const float* __restrict__ avg_w,    // [8,1,11] flat; band-0 taps (uniform)
    const float* __restrict__ avg_b,
    const float* __restrict__ mix_w,
    const float* __restrict__ gauss_w,  // [1,1,15] flat
    const float* __restrict__ gauss_b,
    float* __restrict__ out)
{
    __shared__ float su[ACHUNK + 2 * UH];
    __shared__ float sm[ACHUNK + 2 * MH];
    __shared__ float sred[8];

    const int b   = blockIdx.y;
    const int t0  = blockIdx.x * ACHUNK;
    const int tid = threadIdx.x;

    // prologue: reads only kernel inputs (not k_pool outputs) — overlaps drain
    float mw[NBANDS];
    #pragma unroll
    for (int c = 0; c < NBANDS; ++c) mw[c] = mix_w[c];
    float aw[NAVG];
    #pragma unroll
    for (int k = 0; k < NAVG; ++k) aw[k] = avg_w[k];
    float CB = 0.f;
    #pragma unroll
    for (int c = 0; c < NBANDS; ++c) CB = fmaf(mw[c], avg_b[c], CB);
    float gw[NGAUSS];
    #pragma unroll
    for (int k = 0; k < NGAUSS; ++k) gw[k] = gauss_w[k];
    const float gb = gauss_b[0];

    // wait for k_pool's grid; makes g_pool/g_bmax/g_sync writes visible
    cudaGridDependencySynchronize();

    const float* pb = g_pool + (size_t)b * NBANDS * TLEN;

    // stage u chunk + halo (zero-padded outside [0, TLEN))
    for (int i = tid; i < ACHUNK + 2 * UH; i += 256) {
        const int gt = t0 - UH + i;
        float v = 0.f;
        if (gt >= 0 && gt < TLEN) {
            #pragma unroll
            for (int c = 0; c < NBANDS; ++c)
                v = fmaf(mw[c], pb[c * TLEN + gt], v);
        }
        su[i] = v;
    }
    __syncthreads();

    // m chunk + halo (m zero-padded outside [0, TLEN) for the gauss conv)
    for (int i = tid; i < ACHUNK + 2 * MH; i += 256) {
        const int gt = t0 - MH + i;
        float mval = 0.f;
        if (gt >= 0 && gt < TLEN) {
            const int bidx = i + (UH - MH);   // su index of global gt
            float a = 0.f;
            #pragma unroll
            for (int k = 0; k < NAVG; ++k)
                a = fmaf(aw[k], su[bidx + k - 5], a);
            mval = su[bidx] - a - CB;
        }
        sm[i] = mval;
    }
    __syncthreads();

    float mx = 0.f;
    float av[ACHUNK / 256];
    #pragma unroll
    for (int j = 0; j < ACHUNK / 256; ++j) {
        const int tl = tid + j * 256;
        float g = gb;
        #pragma unroll
        for (int k = 0; k < NGAUSS; ++k)
            g = fmaf(gw[k], sm[tl + k], g);
        const float a = fmaxf(g, 0.f);
        av[j] = a;
        mx = fmaxf(mx, a);
    }

    // block max -> atomicMax (values >= 0, so uint order == float order)
    #pragma unroll
    for (int o = 16; o > 0; o >>= 1)
        mx = fmaxf(mx, __shfl_xor_sync(0xffffffffu, mx, o));
    if ((tid & 31) == 0) sred[tid >> 5] = mx;
    __syncthreads();

    // 128-block spin barrier (1 block per SM; all co-resident post-PDL)
    if (tid == 0) {
        mx = fmaxf(fmaxf(fmaxf(sred[0], sred[1]), fmaxf(sred[2], sred[3])),
                   fmaxf(fmaxf(sred[4], sred[5]), fmaxf(sred[6], sred[7])));
        atomicMax(&g_bmax[b], __float_as_uint(mx));
        __threadfence();                      // publish my max before arriving
        atomicAdd(&g_sync, 1u);               // arrive
        volatile unsigned* v = &g_sync;
        while (*v < (unsigned)NBLK_TAIL) { }
    }
    __syncthreads();

    const float mxv = __uint_as_float(*(volatile unsigned*)&g_bmax[b]);
    const float inv = 1.0f / (mxv + 1e-8f);

    float* ob = out + (size_t)b * TLEN + t0;
    #pragma unroll
    for (int j = 0; j < ACHUNK / 256; ++j)
        ob[tid + j * 256] = av[j] * inv;
}

// ---------------------------------------------------------------------------
// Inputs (metadata order): x, log_gamma, diff_w, diff_b, avg_w, avg_b,
//                          mix_w, gauss_w, gauss_b. Output: [8, 16384] fp32.
// ---------------------------------------------------------------------------
extern "C" void kernel_launch(void* const* d_in, const int* in_sizes, int n_in,
                              void* d_out, int out_size)
{
    const float* x         = (const float*)d_in[0];
    const float* log_gamma = (const float*)d_in[1];
    const float* diff_w    = (const float*)d_in[2];
    const float* diff_b    = (const float*)d_in[3];
    const float* avg_w     = (const float*)d_in[4];
    const float* avg_b     = (const float*)d_in[5];
    const float* mix_w     = (const float*)d_in[6];
    const float* gauss_w   = (const float*)d_in[7];
    const float* gauss_b   = (const float*)d_in[8];
    float* out = (float*)d_out;

    // 2048 blocks x 64 threads: the converged streamer configuration.
    k_pool<<<dim3(TLEN / STRIP, BATCH * NBANDS), TPB_POOL>>>(x, log_gamma, diff_w, diff_b);

    // PDL: hide the fused tail's launch ramp + prologue under k_pool's drain.
    cudaLaunchAttribute pdl[1];
    pdl[0].id = cudaLaunchAttributeProgrammaticStreamSerialization;
    pdl[0].val.programmaticStreamSerializationAllowed = 1;

    cudaLaunchConfig_t cfg = {};
    cfg.gridDim  = dim3(TLEN / ACHUNK, BATCH);   // 16 x 8 = 128 blocks
    cfg.blockDim = dim3(256);
    cfg.attrs    = pdl;
    cfg.numAttrs = 1;
    cudaLaunchKernelEx(&cfg, k_tail, avg_w, avg_b, mix_w, gauss_w, gauss_b, out);
}

// round 17
// speedup vs baseline: 1.2618x; 1.0309x over previous
#include <cuda_runtime.h>
#include <cstdint>

// Problem constants (fixed by setup_inputs): x is [8, 512, 16384] fp32.
#define BATCH   8
#define NBANDS  8
#define FBAND   64          // 512 / 8
#define TLEN    16384
#define NDIFF   5
#define NAVG    11
#define NGAUSS  15
#define STRIP   512         // time-strip per k_pool block (64 thr * 8 t)
#define TPB_POOL 64

// Scratch (allocation-free rule: __device__ globals)
__device__ float    g_pool[BATCH * NBANDS * TLEN];   // 4 MB
__device__ float    g_act [BATCH * TLEN];            // 512 KB
__device__ unsigned g_bmax[BATCH];
__device__ __align__(8) float g_zero2[2] = {0.f, 0.f};  // zero-pad page for halos

// log2(1 + gam*v); ln2 is folded into the diff weights so no FMUL-by-ln2 here.
__device__ __forceinline__ float lg2p(float gam, float v) {
    return __log2f(fmaf(gam, v, 1.0f));
}

// ---------------------------------------------------------------------------
// Kernel 1: the 256 MB streamer — converged configuration (44.1us, 6.27 TB/s
// ~= LTS chip cap; reproduced in rounds 8, 11, 13, 16).
// pool[b,c,t] = sum_f relu( sum_k diff_w[c,k]*log1p(gamma_c*x[b,c*64+f,t+k-2]) + diff_b[c] )
// Thread owns 8 contiguous t: 2x LDG.128 + 1 halo float per row, 9 logs/row,
// 1-row-deep manual load pipeline. 2048 blocks x 64 threads.
// ---------------------------------------------------------------------------
__global__ void __launch_bounds__(TPB_POOL, 16) k_pool(
    const float* __restrict__ x,
    const float* __restrict__ log_gamma,
    const float* __restrict__ diff_w,      // [NBANDS,1,1,5] flat
    const float* __restrict__ diff_b)
{
    const int slab = blockIdx.y;                 // b*NBANDS + c
    const int c    = slab & (NBANDS - 1);
    const int tid  = threadIdx.x;
    const int t0   = blockIdx.x * STRIP + tid * 8;

    // reset per-batch maxes (k_act consumes them after its grid-dependency sync)
    if (blockIdx.x == 0 && blockIdx.y == 0 && tid < BATCH) g_bmax[tid] = 0u;

    const float gam = __expf(log_gamma[c]);
    const float LN2 = 0.69314718055994531f;      // fold ln2 into weights -> log2f
    const float w0 = diff_w[c * NDIFF + 0] * LN2;
    const float w1 = diff_w[c * NDIFF + 1] * LN2;
    const float w2 = diff_w[c * NDIFF + 2] * LN2;
    const float w3 = diff_w[c * NDIFF + 3] * LN2;
    const float w4 = diff_w[c * NDIFF + 4] * LN2;
    const float db = diff_b[c];

    const float* base = x + (size_t)slab * FBAND * TLEN + t0;

    const bool okR = (t0 + 8 < TLEN);

    float acc[8];
    #pragma unroll
    for (int i = 0; i < 8; ++i) acc[i] = 0.f;

    if (w0 == 0.f && w1 == 0.f && w4 == 0.f) {
        // ---------------- sparse hot path: taps 2,3 only ----------------
        // outputs i use logs of t0+i .. t0+i+1 -> window [t0, t0+9): only ONE
        // right-halo float needed; left halo not needed at all.
        const float* pR = okR ? (base + 8) : g_zero2;
        const int    sR = okR ? TLEN : 0;

        float4 a0 = __ldcs(reinterpret_cast<const float4*>(base));
        float4 b0 = __ldcs(reinterpret_cast<const float4*>(base + 4));
        float  r0 = __ldcs(pR);

        #pragma unroll 2
        for (int f = 0; f < FBAND; ++f) {
            const int fn = (f + 1) & (FBAND - 1);   // wrap-clamped prefetch
            const float4 a1 = __ldcs(reinterpret_cast<const float4*>(base + (size_t)fn * TLEN));
            const float4 b1 = __ldcs(reinterpret_cast<const float4*>(base + (size_t)fn * TLEN + 4));
            const float  r1 = __ldcs(pR + (size_t)fn * sR);

            // L[j] = log2(1 + gamma * x[t0 + j]), j = 0..8 (zero page -> 0)
            float L[9];
            L[0] = lg2p(gam, a0.x);  L[1] = lg2p(gam, a0.y);
            L[2] = lg2p(gam, a0.z);  L[3] = lg2p(gam, a0.w);
            L[4] = lg2p(gam, b0.x);  L[5] = lg2p(gam, b0.y);
            L[6] = lg2p(gam, b0.z);  L[7] = lg2p(gam, b0.w);
            L[8] = lg2p(gam, r0);

            #pragma unroll
            for (int i = 0; i < 8; ++i) {
                // d = w2*log[t+0] + w3*log[t+1] + db  (w0=w1=w4=0 exactly)
                float d = fmaf(w2, L[i], fmaf(w3, L[i + 1], db));
                acc[i] += fmaxf(d, 0.f);   // A_LRELU = 0 -> relu
            }
            a0 = a1; b0 = b1; r0 = r1;
        }
    } else {
        // ------------- general fallback (arbitrary 5-tap weights) -------------
        // Register-light scalar path; correct for any diff_w. Never taken for
        // this problem's weights, so performance is irrelevant.
        const float wk[NDIFF] = {w0, w1, w2, w3, w4};
        for (int f = 0; f < FBAND; ++f) {
            const float* p = base + (size_t)f * TLEN;
            #pragma unroll
            for (int i = 0; i < 8; ++i) {
                float d = db;
                #pragma unroll
                for (int k = 0; k < NDIFF; ++k) {
                    const int t = t0 + i + k - 2;
                    float lv = 0.f;
                    if (t >= 0 && t < TLEN)
                        lv = lg2p(gam, __ldg(p + (i + k - 2)));
                    d = fmaf(wk[k], lv, d);
                }
                acc[i] += fmaxf(d, 0.f);
            }
        }
    }

    float* o = g_pool + (size_t)slab * TLEN + t0;
    *reinterpret_cast<float4*>(o)     = make_float4(acc[0], acc[1], acc[2], acc[3]);
    *reinterpret_cast<float4*>(o + 4) = make_float4(acc[4], acc[5], acc[6], acc[7]);
}

// ---------------------------------------------------------------------------
// Kernel 2: mix + avg + gauss + relu + per-batch max. Wide grid (16 x 8 blocks).
// Launched with PDL: prologue (weight loads) overlaps k_pool's drain; the
// grid-dependency sync gates only the g_pool/g_bmax accesses.
// ---------------------------------------------------------------------------
#define ACHUNK 1024
#define UH 12      // 5 (avg) + 7 (gauss)
#define MH 7

__global__ void __launch_bounds__(256) k_act(
    const float* __restrict__ avg_w,    // [8,1,11] flat; band-0 taps (uniform)
    const float* __restrict__ avg_b,
    const float* __restrict__ mix_w,
    const float* __restrict__ gauss_w,  // [1,1,15] flat
    const float* __restrict__ gauss_b)
{
    __shared__ float su[ACHUNK + 2 * UH];
    __shared__ float sm[ACHUNK + 2 * MH];
    __shared__ float sred[8];

    const int b   = blockIdx.y;
    const int t0  = blockIdx.x * ACHUNK;
    const int tid = threadIdx.x;

    // prologue: everything here reads only kernel inputs (not k_pool outputs)
    float mw[NBANDS];
    #pragma unroll
    for (int c = 0; c < NBANDS; ++c) mw[c] = mix_w[c];
    float aw[NAVG];
    #pragma unroll
    for (int k = 0; k < NAVG; ++k) aw[k] = avg_w[k];
    float CB = 0.f;
    #pragma unroll
    for (int c = 0; c < NBANDS; ++c) CB = fmaf(mw[c], avg_b[c], CB);
    float gw[NGAUSS];
    #pragma unroll
    for (int k = 0; k < NGAUSS; ++k) gw[k] = gauss_w[k];
    const float gb = gauss_b[0];

    // wait for k_pool's grid (PDL); makes its g_pool/g_bmax writes visible
    cudaGridDependencySynchronize();

    const float* pb = g_pool + (size_t)b * NBANDS * TLEN;

    // stage u chunk + halo (zero-padded outside [0, TLEN)); u computed on the fly
    for (int i = tid; i < ACHUNK + 2 * UH; i += 256) {
        const int gt = t0 - UH + i;
        float v = 0.f;
        if (gt >= 0 && gt < TLEN) {
            #pragma unroll
            for (int c = 0; c < NBANDS; ++c)
                v = fmaf(mw[c], pb[c * TLEN + gt], v);
        }
        su[i] = v;
    }
    __syncthreads();

    // m chunk + halo (m zero-padded outside [0, TLEN) for the gauss conv)
    for (int i = tid; i < ACHUNK + 2 * MH; i += 256) {
        const int gt = t0 - MH + i;
        float mval = 0.f;
        if (gt >= 0 && gt < TLEN) {
            const int bidx = i + (UH - MH);   // su index of global gt
            float a = 0.f;
            #pragma unroll
            for (int k = 0; k < NAVG; ++k)
                a = fmaf(aw[k], su[bidx + k - 5], a);
            mval = su[bidx] - a - CB;
        }
        sm[i] = mval;
    }
    __syncthreads();

    float mx = 0.f;
    float* ao = g_act + (size_t)b * TLEN + t0;
    #pragma unroll
    for (int j = 0; j < ACHUNK / 256; ++j) {
        const int tl = tid + j * 256;
        float g = gb;
        #pragma unroll
        for (int k = 0; k < NGAUSS; ++k)
            g = fmaf(gw[k], sm[tl + k], g);
        const float a = fmaxf(g, 0.f);
        ao[tl] = a;
        mx = fmaxf(mx, a);
    }

    // block max reduce -> atomicMax (values >= 0, so uint order == float order)
    #pragma unroll
    for (int o = 16; o > 0; o >>= 1)
        mx = fmaxf(mx, __shfl_xor_sync(0xffffffffu, mx, o));
    if ((tid & 31) == 0) sred[tid >> 5] = mx;
    __syncthreads();
    if (tid < 8) {
        mx = sred[tid];
        #pragma unroll
        for (int o = 4; o > 0; o >>= 1)
            mx = fmaxf(mx, __shfl_xor_sync(0xffu, mx, o));
        if (tid == 0) atomicMax(&g_bmax[b], __float_as_uint(mx));
    }
}

// ---------------------------------------------------------------------------
// Kernel 3: out = act / (max_b + 1e-8). Also PDL-gated on k_act.
// ---------------------------------------------------------------------------
__global__ void __launch_bounds__(256) k_norm(float* __restrict__ out)
{
    const int v = blockIdx.x * 256 + threadIdx.x;   // float4 index over BATCH*TLEN/4
    const int b = v / (TLEN / 4);

    cudaGridDependencySynchronize();   // wait for k_act's g_act / g_bmax

    const float mxv = __uint_as_float(g_bmax[b]);
    const float inv = 1.0f / (mxv + 1e-8f);
    float4 q = reinterpret_cast<const float4*>(g_act)[v];
    q.x *= inv; q.y *= inv; q.z *= inv; q.w *= inv;
    reinterpret_cast<float4*>(out)[v] = q;
}

// ---------------------------------------------------------------------------
// Inputs (metadata order): x, log_gamma, diff_w, diff_b, avg_w, avg_b,
//                          mix_w, gauss_w, gauss_b. Output: [8, 16384] fp32.
// ---------------------------------------------------------------------------
extern "C" void kernel_launch(void* const* d_in, const int* in_sizes, int n_in,
                              void* d_out, int out_size)
{
    const float* x         = (const float*)d_in[0];
    const float* log_gamma = (const float*)d_in[1];
    const float* diff_w    = (const float*)d_in[2];
    const float* diff_b    = (const float*)d_in[3];
    const float* avg_w     = (const float*)d_in[4];
    const float* avg_b     = (const float*)d_in[5];
    const float* mix_w     = (const float*)d_in[6];
    const float* gauss_w   = (const float*)d_in[7];
    const float* gauss_b   = (const float*)d_in[8];
    float* out = (float*)d_out;

    // 2048 blocks x 64 threads: the converged streamer configuration.
    k_pool<<<dim3(TLEN / STRIP, BATCH * NBANDS), TPB_POOL>>>(x, log_gamma, diff_w, diff_b);

    // PDL: overlap tail-kernel launch ramps with the upstream kernel's drain.
    cudaLaunchAttribute pdl[1];
    pdl[0].id = cudaLaunchAttributeProgrammaticStreamSerialization;
    pdl[0].val.programmaticStreamSerializationAllowed = 1;

    {
        cudaLaunchConfig_t cfg = {};
        cfg.gridDim  = dim3(TLEN / ACHUNK, BATCH);
        cfg.blockDim = dim3(256);
        cfg.attrs    = pdl;
        cfg.numAttrs = 1;
        cudaLaunchKernelEx(&cfg, k_act, avg_w, avg_b, mix_w, gauss_w, gauss_b);
    }
    {
        cudaLaunchConfig_t cfg = {};
        cfg.gridDim  = dim3(BATCH * TLEN / 4 / 256);
        cfg.blockDim = dim3(256);
        cfg.attrs    = pdl;
        cfg.numAttrs = 1;
        cudaLaunchKernelEx(&cfg, k_norm, out);
    }
}